// round 9
// baseline (speedup 1.0000x reference)
#include <cuda_runtime.h>
#include <cuda_bf16.h>
#include <math.h>

#define Hs   128
#define Ws   128
#define Cs   64
#define Os   64
#define HW   16384
#define Q    576          // Cs * 9
#define NP   24           // padded N for offset conv

typedef unsigned long long u64;
typedef unsigned int u32;

// offsets, layout [k][b*HW] as u64 (dy,dx) pairs
__device__ u64 g_off[9 * 4 * HW];
// bf16-split deform weights: [k][o][c]
__device__ __align__(16) __nv_bfloat16 g_whi[9 * 64 * 64];
__device__ __align__(16) __nv_bfloat16 g_wlo[9 * 64 * 64];
// bf16-split offset-conv weights: [k][n(24)][c]
__device__ __align__(16) __nv_bfloat16 g_wohi[9 * NP * 64];
__device__ __align__(16) __nv_bfloat16 g_wolo[9 * NP * 64];

// ---------------- helpers ----------------
__device__ __forceinline__ u64 pack2(float lo, float hi) {
    u64 r;
    asm("mov.b64 %0, {%1, %2};" : "=l"(r) : "f"(lo), "f"(hi));
    return r;
}
__device__ __forceinline__ void unpack2(u64 v, float& lo, float& hi) {
    asm("mov.b64 {%0, %1}, %2;" : "=f"(lo), "=f"(hi) : "l"(v));
}

#define SMEM_SWIZZLE_128B(o) ((o) ^ (((o) >> 3) & 0x70))

__device__ __forceinline__ void hmma(float* d, const u32* a, const u32* b) {
    asm volatile(
        "mma.sync.aligned.m16n8k16.row.col.f32.bf16.bf16.f32 "
        "{%0,%1,%2,%3}, {%4,%5,%6,%7}, {%8,%9}, {%0,%1,%2,%3};"
        : "+f"(d[0]), "+f"(d[1]), "+f"(d[2]), "+f"(d[3])
        : "r"(a[0]), "r"(a[1]), "r"(a[2]), "r"(a[3]), "r"(b[0]), "r"(b[1]));
}

__device__ __forceinline__ void split_bf16(float v, __nv_bfloat16& h, __nv_bfloat16& l) {
    h = __float2bfloat16(v);
    l = __float2bfloat16(v - __bfloat162float(h));
}

// ================= Kernel 0: split both weight sets to bf16 hi/lo =================
__global__ void wsplit_kernel(const float* __restrict__ wd,
                              const float* __restrict__ wo) {
    int i = blockIdx.x * 256 + threadIdx.x;
    if (i < 9 * 64 * 64) {
        int k = i >> 12;
        int r = i & 4095;
        int o = r >> 6;
        int c = r & 63;
        float v = wd[o * Q + c * 9 + k];
        __nv_bfloat16 h, l;
        split_bf16(v, h, l);
        g_whi[i] = h;
        g_wlo[i] = l;
    } else if (i < 9 * 64 * 64 + 9 * NP * 64) {
        int j = i - 9 * 64 * 64;
        int k = j / (NP * 64);
        int r = j - k * (NP * 64);
        int n = r >> 6;
        int c = r & 63;
        float v = (n < 18) ? wo[n * Q + c * 9 + k] : 0.0f;
        __nv_bfloat16 h, l;
        split_bf16(v, h, l);
        g_wohi[j] = h;
        g_wolo[j] = l;
    }
}

// ================= Kernel 1: offset conv, patch-based, barrier-free k-loop =================
// Patch: channel-last bf16 (hi only) [3 ky][132 xx][72 c-pad], row = 144 B.
//   patch[ky][xx][c] = x[c][h-1+ky][xx-1]  (zero outside image)
// A fragment [m][c] for k = patch[kh][m+kw][c]; banks (4g+tig) conflict-free.
// All 9 W chunks (hi/lo, SW128) staged upfront. One __syncthreads total before GEMM.
static constexpr int OP_PB   = 0;                       // 57024 B patch
static constexpr int OP_WHI  = 57088;                   // 9*24*128 = 27648
static constexpr int OP_WLO  = 84736;                   // 27648
static constexpr int OP_TOT  = 112384;

__global__ void __launch_bounds__(256, 2)
offset_mma_kernel(const float* __restrict__ x,
                  const float* __restrict__ bo) {
    extern __shared__ __align__(1024) char smem[];

    int t    = threadIdx.x;
    int wid  = t >> 5;
    int lane = t & 31;
    int g    = lane >> 2;
    int tig  = lane & 3;

    int tile = blockIdx.x;
    int h = tile & 127;
    int b = tile >> 7;
    const float* xb = x + (size_t)b * Cs * HW;

    int m0 = wid * 16;

    // ---- stage all 9 W chunks (hi/lo), SW128, 128B rows ----
    for (int j = t; j < 1728; j += 256) {            // 9*24*8 uint4
        int k  = j / 192;
        int r  = j - k * 192;
        int n  = r >> 3;
        int c8 = r & 7;
        u32 dst = (u32)(k * 3072) + SMEM_SWIZZLE_128B((u32)(n * 128 + c8 * 16));
        *(uint4*)(smem + OP_WHI + dst) =
            *(const uint4*)(g_wohi + k * 1536 + n * 64 + c8 * 8);
        *(uint4*)(smem + OP_WLO + dst) =
            *(const uint4*)(g_wolo + k * 1536 + n * 64 + c8 * 8);
    }

    // ---- stage patch: 3 x 130 x 64 elements, coalesced LDG over xx ----
    for (int idx = t; idx < 3 * 130 * 64; idx += 256) {
        int xx = idx % 130;
        int r  = idx / 130;
        int c  = r & 63;
        int ky = r >> 6;
        int col = xx - 1;
        int y   = h - 1 + ky;
        float v = 0.0f;
        if (y >= 0 && y < Hs && col >= 0 && col < Ws)
            v = __ldg(xb + (size_t)c * HW + y * Ws + col);
        *(__nv_bfloat16*)(smem + OP_PB + ((ky * 132 + xx) * 72 + c) * 2) =
            __float2bfloat16(v);
    }
    __syncthreads();

    // ---- GEMM: 9 k-chunks, no barriers ----
    float acc[3][4];
#pragma unroll
    for (int nt = 0; nt < 3; nt++)
#pragma unroll
        for (int j = 0; j < 4; j++) acc[nt][j] = 0.0f;

#pragma unroll 1
    for (int k = 0; k < 9; k++) {
        int kh = k / 3, kw = k - kh * 3;
        int rowA = (kh * 132 + kw + m0 + g) * 144;     // bytes
#pragma unroll
        for (int ks = 0; ks < 4; ks++) {
            int cb = ks * 32 + tig * 4;
            u32 a[4];
            a[0] = *(const u32*)(smem + OP_PB + rowA + cb);
            a[1] = *(const u32*)(smem + OP_PB + rowA + 1152 + cb);   // +8 rows
            a[2] = *(const u32*)(smem + OP_PB + rowA + cb + 16);
            a[3] = *(const u32*)(smem + OP_PB + rowA + 1152 + cb + 16);
            u32 kb = (u32)cb;
#pragma unroll
            for (int nt = 0; nt < 3; nt++) {
                u32 nr = (u32)((nt * 8 + g) * 128) + (u32)(k * 3072);
                u32 b_hi[2], b_lo[2];
                b_hi[0] = *(const u32*)(smem + OP_WHI + ((u32)(k*3072)) + SMEM_SWIZZLE_128B((u32)((nt*8+g)*128) + kb));
                b_hi[1] = *(const u32*)(smem + OP_WHI + ((u32)(k*3072)) + SMEM_SWIZZLE_128B((u32)((nt*8+g)*128) + kb + 16));
                b_lo[0] = *(const u32*)(smem + OP_WLO + ((u32)(k*3072)) + SMEM_SWIZZLE_128B((u32)((nt*8+g)*128) + kb));
                b_lo[1] = *(const u32*)(smem + OP_WLO + ((u32)(k*3072)) + SMEM_SWIZZLE_128B((u32)((nt*8+g)*128) + kb + 16));
                (void)nr;
                hmma(acc[nt], a, b_hi);
                hmma(acc[nt], a, b_lo);
            }
        }
    }
    __syncthreads();   // all patch reads done before epilogue overwrites it

    // ---- epilogue: transpose via smem, pack (dy,dx) into g_off[k][P] ----
    float* O = (float*)smem;       // [24 n][132 m]
#pragma unroll
    for (int nt = 0; nt < 3; nt++) {
        int n = nt * 8 + tig * 2;
        int m = m0 + g;
        O[n * 132 + m]            = acc[nt][0];
        O[(n + 1) * 132 + m]      = acc[nt][1];
        O[n * 132 + m + 8]        = acc[nt][2];
        O[(n + 1) * 132 + m + 8]  = acc[nt][3];
    }
    __syncthreads();

    int Pbase = tile * 128;
    for (int i = t; i < 9 * 128; i += 256) {
        int k2 = i >> 7;
        int m  = i & 127;
        float dy = O[(2 * k2) * 132 + m]     + __ldg(bo + 2 * k2);
        float dx = O[(2 * k2 + 1) * 132 + m] + __ldg(bo + 2 * k2 + 1);
        g_off[k2 * 4 * HW + Pbase + m] = pack2(dy, dx);
    }
}

// ================= Kernel 2: deformable conv, double-buffered, 1 sync/k =================
// S buffers: [2][hi 16K + lo 16K] @0; W buffers: [2][hi 8K + lo 8K] @65536.
static constexpr int SM_SHI = 0;         // + buf*32768
static constexpr int SM_SLO = 16384;     // + buf*32768
static constexpr int SM_WHI = 65536;     // + buf*16384
static constexpr int SM_WLO = 73728;     // + buf*16384
static constexpr int SM_TOT = 98304;

__global__ void __launch_bounds__(256, 2)
deform_mma_kernel(const float* __restrict__ x,
                  const float* __restrict__ bd,
                  float* __restrict__ out) {
    extern __shared__ __align__(1024) char smem[];

    int t    = threadIdx.x;
    int wid  = t >> 5;
    int lane = t & 31;
    int g    = lane >> 2;
    int tig  = lane & 3;

    int tile = blockIdx.x;
    int h = tile & 127;
    int b = tile >> 7;
    const float* xb = x + (size_t)b * Cs * HW;

    int spx   = t & 127;
    int cbase = (t >> 7) * 32;
    int P     = tile * 128 + spx;
    int m0    = wid * 16;

    float acc[8][4];
#pragma unroll
    for (int nt = 0; nt < 8; nt++)
#pragma unroll
        for (int j = 0; j < 4; j++) acc[nt][j] = 0.0f;

#pragma unroll 1
    for (int k = 0; k < 9; k++) {
        int sbuf = (k & 1) * 32768;
        int wbuf = (k & 1) * 16384;

        // ---- stage W chunk into wbuf ----
        for (int j = t; j < 512; j += 256) {
            int n  = j >> 3;
            int c8 = j & 7;
            u32 dst = SMEM_SWIZZLE_128B((u32)(n * 128 + c8 * 16));
            *(uint4*)(smem + SM_WHI + wbuf + dst) =
                *(const uint4*)(g_whi + k * 4096 + n * 64 + c8 * 8);
            *(uint4*)(smem + SM_WLO + wbuf + dst) =
                *(const uint4*)(g_wlo + k * 4096 + n * 64 + c8 * 8);
        }

        // ---- sample 32 channels, split bf16, STS into sbuf ----
        {
            int kh = k / 3, kw = k - kh * 3;
            float dlo, dhi;
            unpack2(g_off[k * 4 * HW + P], dlo, dhi);
            float py = (float)(h - 1 + kh) + dlo;
            float px = (float)(spx - 1 + kw) + dhi;
            float y0f = floorf(py), x0f = floorf(px);
            int y0 = (int)y0f, x0 = (int)x0f;
            int y1 = y0 + 1,   x1 = x0 + 1;
            float wy1 = py - y0f, wy0 = 1.0f - wy1;
            float wx1 = px - x0f, wx0 = 1.0f - wx1;
            float vy0 = (y0 >= 0 && y0 < Hs) ? 1.0f : 0.0f;
            float vy1 = (y1 >= 0 && y1 < Hs) ? 1.0f : 0.0f;
            float vx0 = (x0 >= 0 && x0 < Ws) ? 1.0f : 0.0f;
            float vx1 = (x1 >= 0 && x1 < Ws) ? 1.0f : 0.0f;
            float w00 = wy0 * wx0 * vy0 * vx0;
            float w01 = wy0 * wx1 * vy0 * vx1;
            float w10 = wy1 * wx0 * vy1 * vx0;
            float w11 = wy1 * wx1 * vy1 * vx1;
            int cy0 = min(max(y0, 0), Hs - 1), cy1 = min(max(y1, 0), Hs - 1);
            int cx0 = min(max(x0, 0), Ws - 1), cx1 = min(max(x1, 0), Ws - 1);
            int o00 = cy0 * Ws + cx0, o01 = cy0 * Ws + cx1;
            int o10 = cy1 * Ws + cx0, o11 = cy1 * Ws + cx1;

#pragma unroll
            for (int gq = 0; gq < 4; gq++) {
                int c0 = cbase + gq * 8;
                const float* xc = xb + (size_t)c0 * HW;
                float s[8];
#pragma unroll
                for (int j = 0; j < 8; j++) {
                    s[j] = fmaf(w00, __ldg(xc + o00),
                           fmaf(w01, __ldg(xc + o01),
                           fmaf(w10, __ldg(xc + o10), w11 * __ldg(xc + o11))));
                    xc += HW;
                }
                u32 hh[4], ll[4];
#pragma unroll
                for (int j2 = 0; j2 < 4; j2++) {
                    float se = s[2 * j2], so = s[2 * j2 + 1];
                    __nv_bfloat16 he, le, ho, lo2;
                    split_bf16(se, he, le);
                    split_bf16(so, ho, lo2);
                    hh[j2] = (u32)__bfloat16_as_ushort(he) |
                             ((u32)__bfloat16_as_ushort(ho) << 16);
                    ll[j2] = (u32)__bfloat16_as_ushort(le) |
                             ((u32)__bfloat16_as_ushort(lo2) << 16);
                }
                u32 off = SMEM_SWIZZLE_128B((u32)(spx * 128 + c0 * 2));
                *(uint4*)(smem + SM_SHI + sbuf + off) = make_uint4(hh[0], hh[1], hh[2], hh[3]);
                *(uint4*)(smem + SM_SLO + sbuf + off) = make_uint4(ll[0], ll[1], ll[2], ll[3]);
            }
        }
        __syncthreads();

        // ---- GEMM chunk from sbuf/wbuf ----
#pragma unroll
        for (int ks = 0; ks < 4; ks++) {
            u32 kb = (u32)(ks * 32 + tig * 4);
            u32 r0 = (u32)((m0 + g) * 128);
            u32 r1 = (u32)((m0 + 8 + g) * 128);
            u32 a_hi[4], a_lo[4];
            a_hi[0] = *(const u32*)(smem + SM_SHI + sbuf + SMEM_SWIZZLE_128B(r0 + kb));
            a_hi[1] = *(const u32*)(smem + SM_SHI + sbuf + SMEM_SWIZZLE_128B(r1 + kb));
            a_hi[2] = *(const u32*)(smem + SM_SHI + sbuf + SMEM_SWIZZLE_128B(r0 + kb + 16));
            a_hi[3] = *(const u32*)(smem + SM_SHI + sbuf + SMEM_SWIZZLE_128B(r1 + kb + 16));
            a_lo[0] = *(const u32*)(smem + SM_SLO + sbuf + SMEM_SWIZZLE_128B(r0 + kb));
            a_lo[1] = *(const u32*)(smem + SM_SLO + sbuf + SMEM_SWIZZLE_128B(r1 + kb));
            a_lo[2] = *(const u32*)(smem + SM_SLO + sbuf + SMEM_SWIZZLE_128B(r0 + kb + 16));
            a_lo[3] = *(const u32*)(smem + SM_SLO + sbuf + SMEM_SWIZZLE_128B(r1 + kb + 16));
#pragma unroll
            for (int nt = 0; nt < 8; nt++) {
                u32 nr = (u32)((nt * 8 + g) * 128);
                u32 b_hi[2], b_lo[2];
                b_hi[0] = *(const u32*)(smem + SM_WHI + wbuf + SMEM_SWIZZLE_128B(nr + kb));
                b_hi[1] = *(const u32*)(smem + SM_WHI + wbuf + SMEM_SWIZZLE_128B(nr + kb + 16));
                b_lo[0] = *(const u32*)(smem + SM_WLO + wbuf + SMEM_SWIZZLE_128B(nr + kb));
                b_lo[1] = *(const u32*)(smem + SM_WLO + wbuf + SMEM_SWIZZLE_128B(nr + kb + 16));
                hmma(acc[nt], a_hi, b_hi);
                hmma(acc[nt], a_hi, b_lo);
                hmma(acc[nt], a_lo, b_hi);
            }
        }
        // no second barrier: next iteration writes the other buffer
    }
    __syncthreads();   // GEMM(8) reads done before epilogue overwrites smem

    float* O = (float*)smem;       // [64 n][132 m]
#pragma unroll
    for (int nt = 0; nt < 8; nt++) {
        int n = nt * 8 + tig * 2;
        int m = m0 + g;
        O[n * 132 + m]            = acc[nt][0];
        O[(n + 1) * 132 + m]      = acc[nt][1];
        O[n * 132 + m + 8]        = acc[nt][2];
        O[(n + 1) * 132 + m + 8]  = acc[nt][3];
    }
    __syncthreads();

    float* ob = out + (size_t)b * Os * HW + h * 128;
    for (int i = t; i < 64 * 128; i += 256) {
        int o  = i >> 7;
        int w2 = i & 127;
        ob[(size_t)o * HW + w2] = O[o * 132 + w2] + __ldg(bd + o);
    }
}

// ---------------- harness entry ----------------
extern "C" void kernel_launch(void* const* d_in, const int* in_sizes, int n_in,
                              void* d_out, int out_size) {
    const float* x  = (const float*)d_in[0];   // [4,64,128,128]
    const float* wo = (const float*)d_in[1];   // [18,64,3,3]
    const float* bo = (const float*)d_in[2];   // [18]
    const float* wd = (const float*)d_in[3];   // [64,64,3,3]
    const float* bd = (const float*)d_in[4];   // [64]
    float* out = (float*)d_out;                // [4,64,128,128]

    cudaFuncSetAttribute(offset_mma_kernel,
                         cudaFuncAttributeMaxDynamicSharedMemorySize, OP_TOT);
    cudaFuncSetAttribute(deform_mma_kernel,
                         cudaFuncAttributeMaxDynamicSharedMemorySize, SM_TOT);

    wsplit_kernel<<<198, 256>>>(wd, wo);
    offset_mma_kernel<<<512, 256, OP_TOT>>>(x, bo);
    deform_mma_kernel<<<512, 256, SM_TOT>>>(x, bd, out);
}

// round 10
// speedup vs baseline: 1.0154x; 1.0154x over previous
#include <cuda_runtime.h>
#include <cuda_bf16.h>
#include <math.h>

#define Hs   128
#define Ws   128
#define Cs   64
#define Os   64
#define HW   16384
#define Q    576          // Cs * 9
#define NP   24           // padded N for offset conv

typedef unsigned long long u64;
typedef unsigned int u32;

// offsets, layout [k][b*HW] as u64 (dy,dx) pairs
__device__ u64 g_off[9 * 4 * HW];
// bf16-split deform weights: [k][o][c]
__device__ __align__(16) __nv_bfloat16 g_whi[9 * 64 * 64];
__device__ __align__(16) __nv_bfloat16 g_wlo[9 * 64 * 64];
// bf16-split offset-conv weights: [k][n(24)][c]
__device__ __align__(16) __nv_bfloat16 g_wohi[9 * NP * 64];
__device__ __align__(16) __nv_bfloat16 g_wolo[9 * NP * 64];

// ---------------- helpers ----------------
__device__ __forceinline__ u64 pack2(float lo, float hi) {
    u64 r;
    asm("mov.b64 %0, {%1, %2};" : "=l"(r) : "f"(lo), "f"(hi));
    return r;
}
__device__ __forceinline__ void unpack2(u64 v, float& lo, float& hi) {
    asm("mov.b64 {%0, %1}, %2;" : "=f"(lo), "=f"(hi) : "l"(v));
}

#define SMEM_SWIZZLE_128B(o) ((o) ^ (((o) >> 3) & 0x70))

__device__ __forceinline__ void hmma(float* d, const u32* a, const u32* b) {
    asm volatile(
        "mma.sync.aligned.m16n8k16.row.col.f32.bf16.bf16.f32 "
        "{%0,%1,%2,%3}, {%4,%5,%6,%7}, {%8,%9}, {%0,%1,%2,%3};"
        : "+f"(d[0]), "+f"(d[1]), "+f"(d[2]), "+f"(d[3])
        : "r"(a[0]), "r"(a[1]), "r"(a[2]), "r"(a[3]), "r"(b[0]), "r"(b[1]));
}

__device__ __forceinline__ void split_bf16(float v, __nv_bfloat16& h, __nv_bfloat16& l) {
    h = __float2bfloat16(v);
    l = __float2bfloat16(v - __bfloat162float(h));
}

// ================= Kernel 0: split both weight sets to bf16 hi/lo =================
__global__ void wsplit_kernel(const float* __restrict__ wd,
                              const float* __restrict__ wo) {
    int i = blockIdx.x * 256 + threadIdx.x;
    if (i < 9 * 64 * 64) {
        int k = i >> 12;
        int r = i & 4095;
        int o = r >> 6;
        int c = r & 63;
        float v = wd[o * Q + c * 9 + k];
        __nv_bfloat16 h, l;
        split_bf16(v, h, l);
        g_whi[i] = h;
        g_wlo[i] = l;
    } else if (i < 9 * 64 * 64 + 9 * NP * 64) {
        int j = i - 9 * 64 * 64;
        int k = j / (NP * 64);
        int r = j - k * (NP * 64);
        int n = r >> 6;
        int c = r & 63;
        float v = (n < 18) ? wo[n * Q + c * 9 + k] : 0.0f;
        __nv_bfloat16 h, l;
        split_bf16(v, h, l);
        g_wohi[j] = h;
        g_wolo[j] = l;
    }
}

// ================= Kernel 1: offset conv via mma.sync bf16x3 (R8 version) =================
static constexpr int O_SHI = 0;
static constexpr int O_SLO = 16384;
static constexpr int O_WHI = 32768;
static constexpr int O_WLO = 35840;
static constexpr int O_TOT = 38912;

__global__ void __launch_bounds__(256, 2)
offset_mma_kernel(const float* __restrict__ x,
                  const float* __restrict__ bo) {
    extern __shared__ __align__(1024) char smem[];

    int t    = threadIdx.x;
    int wid  = t >> 5;
    int lane = t & 31;
    int g    = lane >> 2;
    int tig  = lane & 3;

    int tile = blockIdx.x;
    int h = tile & 127;
    int b = tile >> 7;
    const float* xb = x + (size_t)b * Cs * HW;

    int spx   = t & 127;
    int cbase = (t >> 7) * 32;
    int m0    = wid * 16;

    float acc[3][4];
#pragma unroll
    for (int nt = 0; nt < 3; nt++)
#pragma unroll
        for (int j = 0; j < 4; j++) acc[nt][j] = 0.0f;

#pragma unroll 1
    for (int k = 0; k < 9; k++) {
        if (t < 192) {
            int n  = t >> 3;
            int c8 = t & 7;
            u32 dst = SMEM_SWIZZLE_128B((u32)(n * 128 + c8 * 16));
            *(uint4*)(smem + O_WHI + dst) =
                *(const uint4*)(g_wohi + k * NP * 64 + n * 64 + c8 * 8);
            *(uint4*)(smem + O_WLO + dst) =
                *(const uint4*)(g_wolo + k * NP * 64 + n * 64 + c8 * 8);
        }

        {
            int kh = k / 3, kw = k - kh * 3;
            int iy = h - 1 + kh;
            int ix = spx - 1 + kw;
            float vf = (iy >= 0 && iy < Hs && ix >= 0 && ix < Ws) ? 1.0f : 0.0f;
            int cy = min(max(iy, 0), Hs - 1);
            int cx = min(max(ix, 0), Ws - 1);
            const float* xp = xb + cy * Ws + cx;

#pragma unroll
            for (int gq = 0; gq < 4; gq++) {
                int c0 = cbase + gq * 8;
                const float* xc = xp + (size_t)c0 * HW;
                u32 hh[4], ll[4];
#pragma unroll
                for (int j2 = 0; j2 < 4; j2++) {
                    float se = __ldg(xc) * vf;              xc += HW;
                    float so = __ldg(xc) * vf;              xc += HW;
                    __nv_bfloat16 he, le, ho, lo2;
                    split_bf16(se, he, le);
                    split_bf16(so, ho, lo2);
                    hh[j2] = (u32)__bfloat16_as_ushort(he) |
                             ((u32)__bfloat16_as_ushort(ho) << 16);
                    ll[j2] = (u32)__bfloat16_as_ushort(le) |
                             ((u32)__bfloat16_as_ushort(lo2) << 16);
                }
                u32 off = SMEM_SWIZZLE_128B((u32)(spx * 128 + c0 * 2));
                *(uint4*)(smem + O_SHI + off) = make_uint4(hh[0], hh[1], hh[2], hh[3]);
                *(uint4*)(smem + O_SLO + off) = make_uint4(ll[0], ll[1], ll[2], ll[3]);
            }
        }
        __syncthreads();

#pragma unroll
        for (int ks = 0; ks < 4; ks++) {
            u32 kb = (u32)(ks * 32 + tig * 4);
            u32 r0 = (u32)((m0 + g) * 128);
            u32 r1 = (u32)((m0 + 8 + g) * 128);
            u32 a_hi[4], a_lo[4];
            a_hi[0] = *(const u32*)(smem + O_SHI + SMEM_SWIZZLE_128B(r0 + kb));
            a_hi[1] = *(const u32*)(smem + O_SHI + SMEM_SWIZZLE_128B(r1 + kb));
            a_hi[2] = *(const u32*)(smem + O_SHI + SMEM_SWIZZLE_128B(r0 + kb + 16));
            a_hi[3] = *(const u32*)(smem + O_SHI + SMEM_SWIZZLE_128B(r1 + kb + 16));
            a_lo[0] = *(const u32*)(smem + O_SLO + SMEM_SWIZZLE_128B(r0 + kb));
            a_lo[1] = *(const u32*)(smem + O_SLO + SMEM_SWIZZLE_128B(r1 + kb));
            a_lo[2] = *(const u32*)(smem + O_SLO + SMEM_SWIZZLE_128B(r0 + kb + 16));
            a_lo[3] = *(const u32*)(smem + O_SLO + SMEM_SWIZZLE_128B(r1 + kb + 16));
#pragma unroll
            for (int nt = 0; nt < 3; nt++) {
                u32 nr = (u32)((nt * 8 + g) * 128);
                u32 b_hi[2], b_lo[2];
                b_hi[0] = *(const u32*)(smem + O_WHI + SMEM_SWIZZLE_128B(nr + kb));
                b_hi[1] = *(const u32*)(smem + O_WHI + SMEM_SWIZZLE_128B(nr + kb + 16));
                b_lo[0] = *(const u32*)(smem + O_WLO + SMEM_SWIZZLE_128B(nr + kb));
                b_lo[1] = *(const u32*)(smem + O_WLO + SMEM_SWIZZLE_128B(nr + kb + 16));
                hmma(acc[nt], a_hi, b_hi);
                hmma(acc[nt], a_hi, b_lo);
                hmma(acc[nt], a_lo, b_hi);
            }
        }
        __syncthreads();
    }

    float* O = (float*)smem;       // [24 n][132 m]
#pragma unroll
    for (int nt = 0; nt < 3; nt++) {
        int n = nt * 8 + tig * 2;
        int m = m0 + g;
        O[n * 132 + m]            = acc[nt][0];
        O[(n + 1) * 132 + m]      = acc[nt][1];
        O[n * 132 + m + 8]        = acc[nt][2];
        O[(n + 1) * 132 + m + 8]  = acc[nt][3];
    }
    __syncthreads();

    int Pbase = tile * 128;
    for (int i = t; i < 9 * 128; i += 256) {
        int k2 = i >> 7;
        int m  = i & 127;
        float dy = O[(2 * k2) * 132 + m]     + __ldg(bo + 2 * k2);
        float dx = O[(2 * k2 + 1) * 132 + m] + __ldg(bo + 2 * k2 + 1);
        g_off[k2 * 4 * HW + Pbase + m] = pack2(dy, dx);
    }
}

// ================= Kernel 2: deformable conv, M=256 (two rows per CTA) =================
// SMEM (81920 B): S_hi[256][64]bf16 @0 (32768), S_lo @32768, W_hi[64][64] @65536 (8192),
//                 W_lo @73728. Epilogue reuses [0, 67584) as float O[64][264].
static constexpr int SM_SHI = 0;
static constexpr int SM_SLO = 32768;
static constexpr int SM_WHI = 65536;
static constexpr int SM_WLO = 73728;
static constexpr int SM_TOT = 81920;

__global__ void __launch_bounds__(256, 2)
deform_mma_kernel(const float* __restrict__ x,
                  const float* __restrict__ bd,
                  float* __restrict__ out) {
    extern __shared__ __align__(1024) char smem[];

    int t    = threadIdx.x;
    int wid  = t >> 5;
    int lane = t & 31;
    int g    = lane >> 2;
    int tig  = lane & 3;

    int tile = blockIdx.x;          // 256 tiles = (b, h-pair)
    int h0 = (tile & 63) * 2;
    int b  = tile >> 6;
    const float* xb = x + (size_t)b * Cs * HW;

    // sampler: thread t -> pixel t of the 2-row tile (all 64 channels)
    int srow = t >> 7;              // 0 or 1
    int spx  = t & 127;
    int h    = h0 + srow;
    int P    = ((b << 7) + h0) * 128 + t;   // global pixel index = b*HW + h*128 + spx

    // GEMM: warp wid covers pixels [wid*32, wid*32+32) (2 m16 tiles)
    int m0 = wid * 32;

    float acc[16][4];
#pragma unroll
    for (int mt = 0; mt < 16; mt++)
#pragma unroll
        for (int j = 0; j < 4; j++) acc[mt][j] = 0.0f;

#pragma unroll 1
    for (int k = 0; k < 9; k++) {
        // ---- stage W chunk ----
        for (int j = t; j < 512; j += 256) {
            int n  = j >> 3;
            int c8 = j & 7;
            u32 dst = SMEM_SWIZZLE_128B((u32)(n * 128 + c8 * 16));
            *(uint4*)(smem + SM_WHI + dst) =
                *(const uint4*)(g_whi + k * 4096 + n * 64 + c8 * 8);
            *(uint4*)(smem + SM_WLO + dst) =
                *(const uint4*)(g_wlo + k * 4096 + n * 64 + c8 * 8);
        }

        // ---- sample all 64 channels for pixel t, split bf16, STS ----
        {
            int kh = k / 3, kw = k - kh * 3;
            float dlo, dhi;
            unpack2(g_off[k * 4 * HW + P], dlo, dhi);
            float py = (float)(h - 1 + kh) + dlo;
            float px = (float)(spx - 1 + kw) + dhi;
            float y0f = floorf(py), x0f = floorf(px);
            int y0 = (int)y0f, x0 = (int)x0f;
            int y1 = y0 + 1,   x1 = x0 + 1;
            float wy1 = py - y0f, wy0 = 1.0f - wy1;
            float wx1 = px - x0f, wx0 = 1.0f - wx1;
            float vy0 = (y0 >= 0 && y0 < Hs) ? 1.0f : 0.0f;
            float vy1 = (y1 >= 0 && y1 < Hs) ? 1.0f : 0.0f;
            float vx0 = (x0 >= 0 && x0 < Ws) ? 1.0f : 0.0f;
            float vx1 = (x1 >= 0 && x1 < Ws) ? 1.0f : 0.0f;
            float w00 = wy0 * wx0 * vy0 * vx0;
            float w01 = wy0 * wx1 * vy0 * vx1;
            float w10 = wy1 * wx0 * vy1 * vx0;
            float w11 = wy1 * wx1 * vy1 * vx1;
            int cy0 = min(max(y0, 0), Hs - 1), cy1 = min(max(y1, 0), Hs - 1);
            int cx0 = min(max(x0, 0), Ws - 1), cx1 = min(max(x1, 0), Ws - 1);
            int o00 = cy0 * Ws + cx0, o01 = cy0 * Ws + cx1;
            int o10 = cy1 * Ws + cx0, o11 = cy1 * Ws + cx1;

#pragma unroll
            for (int gq = 0; gq < 8; gq++) {
                int c0 = gq * 8;
                const float* xc = xb + (size_t)c0 * HW;
                float s[8];
#pragma unroll
                for (int j = 0; j < 8; j++) {
                    s[j] = fmaf(w00, __ldg(xc + o00),
                           fmaf(w01, __ldg(xc + o01),
                           fmaf(w10, __ldg(xc + o10), w11 * __ldg(xc + o11))));
                    xc += HW;
                }
                u32 hh[4], ll[4];
#pragma unroll
                for (int j2 = 0; j2 < 4; j2++) {
                    float se = s[2 * j2], so = s[2 * j2 + 1];
                    __nv_bfloat16 he, le, ho, lo2;
                    split_bf16(se, he, le);
                    split_bf16(so, ho, lo2);
                    hh[j2] = (u32)__bfloat16_as_ushort(he) |
                             ((u32)__bfloat16_as_ushort(ho) << 16);
                    ll[j2] = (u32)__bfloat16_as_ushort(le) |
                             ((u32)__bfloat16_as_ushort(lo2) << 16);
                }
                u32 off = SMEM_SWIZZLE_128B((u32)(t * 128 + c0 * 2));
                *(uint4*)(smem + SM_SHI + off) = make_uint4(hh[0], hh[1], hh[2], hh[3]);
                *(uint4*)(smem + SM_SLO + off) = make_uint4(ll[0], ll[1], ll[2], ll[3]);
            }
        }
        __syncthreads();

        // ---- GEMM chunk: 4 k16-steps x 2 m-tiles x 8 n-tiles x 3 products ----
#pragma unroll
        for (int ks = 0; ks < 4; ks++) {
            u32 kb = (u32)(ks * 32 + tig * 4);
            u32 a_hi[2][4], a_lo[2][4];
#pragma unroll
            for (int mt2 = 0; mt2 < 2; mt2++) {
                u32 r0 = (u32)((m0 + mt2 * 16 + g) * 128);
                u32 r1 = (u32)((m0 + mt2 * 16 + 8 + g) * 128);
                a_hi[mt2][0] = *(const u32*)(smem + SM_SHI + SMEM_SWIZZLE_128B(r0 + kb));
                a_hi[mt2][1] = *(const u32*)(smem + SM_SHI + SMEM_SWIZZLE_128B(r1 + kb));
                a_hi[mt2][2] = *(const u32*)(smem + SM_SHI + SMEM_SWIZZLE_128B(r0 + kb + 16));
                a_hi[mt2][3] = *(const u32*)(smem + SM_SHI + SMEM_SWIZZLE_128B(r1 + kb + 16));
                a_lo[mt2][0] = *(const u32*)(smem + SM_SLO + SMEM_SWIZZLE_128B(r0 + kb));
                a_lo[mt2][1] = *(const u32*)(smem + SM_SLO + SMEM_SWIZZLE_128B(r1 + kb));
                a_lo[mt2][2] = *(const u32*)(smem + SM_SLO + SMEM_SWIZZLE_128B(r0 + kb + 16));
                a_lo[mt2][3] = *(const u32*)(smem + SM_SLO + SMEM_SWIZZLE_128B(r1 + kb + 16));
            }
#pragma unroll
            for (int nt = 0; nt < 8; nt++) {
                u32 nr = (u32)((nt * 8 + g) * 128);
                u32 b_hi[2], b_lo[2];
                b_hi[0] = *(const u32*)(smem + SM_WHI + SMEM_SWIZZLE_128B(nr + kb));
                b_hi[1] = *(const u32*)(smem + SM_WHI + SMEM_SWIZZLE_128B(nr + kb + 16));
                b_lo[0] = *(const u32*)(smem + SM_WLO + SMEM_SWIZZLE_128B(nr + kb));
                b_lo[1] = *(const u32*)(smem + SM_WLO + SMEM_SWIZZLE_128B(nr + kb + 16));
                hmma(acc[nt], a_hi[0], b_hi);
                hmma(acc[nt], a_hi[0], b_lo);
                hmma(acc[nt], a_lo[0], b_hi);
                hmma(acc[8 + nt], a_hi[1], b_hi);
                hmma(acc[8 + nt], a_hi[1], b_lo);
                hmma(acc[8 + nt], a_lo[1], b_hi);
            }
        }
        __syncthreads();
    }

    // ---- epilogue: transpose via smem, coalesced store with bias ----
    float* O = (float*)smem;       // [64 n][264 m]
#pragma unroll
    for (int mt2 = 0; mt2 < 2; mt2++) {
#pragma unroll
        for (int nt = 0; nt < 8; nt++) {
            int n = nt * 8 + tig * 2;
            int m = m0 + mt2 * 16 + g;
            const float* a4 = acc[mt2 * 8 + nt];
            O[n * 264 + m]            = a4[0];
            O[(n + 1) * 264 + m]      = a4[1];
            O[n * 264 + m + 8]        = a4[2];
            O[(n + 1) * 264 + m + 8]  = a4[3];
        }
    }
    __syncthreads();

    float* ob = out + (size_t)b * Os * HW + h0 * 128;
    for (int i = t; i < 64 * 256; i += 256) {
        int o = i >> 8;
        int m = i & 255;               // m = srow*128 + col
        int r = m >> 7, c = m & 127;
        ob[(size_t)o * HW + r * 128 + c] = O[o * 264 + m] + __ldg(bd + o);
    }
}

// ---------------- harness entry ----------------
extern "C" void kernel_launch(void* const* d_in, const int* in_sizes, int n_in,
                              void* d_out, int out_size) {
    const float* x  = (const float*)d_in[0];   // [4,64,128,128]
    const float* wo = (const float*)d_in[1];   // [18,64,3,3]
    const float* bo = (const float*)d_in[2];   // [18]
    const float* wd = (const float*)d_in[3];   // [64,64,3,3]
    const float* bd = (const float*)d_in[4];   // [64]
    float* out = (float*)d_out;                // [4,64,128,128]

    cudaFuncSetAttribute(offset_mma_kernel,
                         cudaFuncAttributeMaxDynamicSharedMemorySize, O_TOT);
    cudaFuncSetAttribute(deform_mma_kernel,
                         cudaFuncAttributeMaxDynamicSharedMemorySize, SM_TOT);

    wsplit_kernel<<<198, 256>>>(wd, wo);
    offset_mma_kernel<<<512, 256, O_TOT>>>(x, bo);
    deform_mma_kernel<<<256, 256, SM_TOT>>>(x, bd, out);
}

// round 11
// speedup vs baseline: 1.1685x; 1.1509x over previous
#include <cuda_runtime.h>
#include <cuda_bf16.h>
#include <math.h>

#define Hs   128
#define Ws   128
#define Cs   64
#define Os   64
#define HW   16384
#define Q    576          // Cs * 9
#define NP   24           // padded N for offset conv

typedef unsigned long long u64;
typedef unsigned int u32;

// offsets, layout [k][b*HW] as u64 (dy,dx) pairs
__device__ u64 g_off[9 * 4 * HW];
// bf16-split deform weights: [k][o][c]
__device__ __align__(16) __nv_bfloat16 g_whi[9 * 64 * 64];
__device__ __align__(16) __nv_bfloat16 g_wlo[9 * 64 * 64];
// bf16-split offset-conv weights: [k][n(24)][c]
__device__ __align__(16) __nv_bfloat16 g_wohi[9 * NP * 64];
__device__ __align__(16) __nv_bfloat16 g_wolo[9 * NP * 64];

// ---------------- helpers ----------------
__device__ __forceinline__ u64 pack2(float lo, float hi) {
    u64 r;
    asm("mov.b64 %0, {%1, %2};" : "=l"(r) : "f"(lo), "f"(hi));
    return r;
}
__device__ __forceinline__ void unpack2(u64 v, float& lo, float& hi) {
    asm("mov.b64 {%0, %1}, %2;" : "=f"(lo), "=f"(hi) : "l"(v));
}
__device__ __forceinline__ u32 smem_u32(const void* p) {
    u32 a;
    asm("{ .reg .u64 t; cvta.to.shared.u64 t, %1; cvt.u32.u64 %0, t; }"
        : "=r"(a) : "l"(p));
    return a;
}

#define SMEM_SWIZZLE_128B(o) ((o) ^ (((o) >> 3) & 0x70))

__device__ __forceinline__ void hmma(float* d, const u32* a, const u32* b) {
    asm volatile(
        "mma.sync.aligned.m16n8k16.row.col.f32.bf16.bf16.f32 "
        "{%0,%1,%2,%3}, {%4,%5,%6,%7}, {%8,%9}, {%0,%1,%2,%3};"
        : "+f"(d[0]), "+f"(d[1]), "+f"(d[2]), "+f"(d[3])
        : "r"(a[0]), "r"(a[1]), "r"(a[2]), "r"(a[3]), "r"(b[0]), "r"(b[1]));
}

__device__ __forceinline__ void ldsm_x4(u32* d, u32 addr) {
    asm volatile("ldmatrix.sync.aligned.m8n8.x4.shared.b16 {%0,%1,%2,%3}, [%4];"
        : "=r"(d[0]), "=r"(d[1]), "=r"(d[2]), "=r"(d[3]) : "r"(addr));
}
__device__ __forceinline__ void ldsm_x2(u32* d, u32 addr) {
    asm volatile("ldmatrix.sync.aligned.m8n8.x2.shared.b16 {%0,%1}, [%2];"
        : "=r"(d[0]), "=r"(d[1]) : "r"(addr));
}

__device__ __forceinline__ void split_bf16(float v, __nv_bfloat16& h, __nv_bfloat16& l) {
    h = __float2bfloat16(v);
    l = __float2bfloat16(v - __bfloat162float(h));
}

// ================= Kernel 0: split both weight sets to bf16 hi/lo =================
__global__ void wsplit_kernel(const float* __restrict__ wd,
                              const float* __restrict__ wo) {
    int i = blockIdx.x * 256 + threadIdx.x;
    if (i < 9 * 64 * 64) {
        int k = i >> 12;
        int r = i & 4095;
        int o = r >> 6;
        int c = r & 63;
        float v = wd[o * Q + c * 9 + k];
        __nv_bfloat16 h, l;
        split_bf16(v, h, l);
        g_whi[i] = h;
        g_wlo[i] = l;
    } else if (i < 9 * 64 * 64 + 9 * NP * 64) {
        int j = i - 9 * 64 * 64;
        int k = j / (NP * 64);
        int r = j - k * (NP * 64);
        int n = r >> 6;
        int c = r & 63;
        float v = (n < 18) ? wo[n * Q + c * 9 + k] : 0.0f;
        __nv_bfloat16 h, l;
        split_bf16(v, h, l);
        g_wohi[j] = h;
        g_wolo[j] = l;
    }
}

// ================= Kernel 1: offset conv via mma.sync bf16x3 + ldmatrix =================
static constexpr int O_SHI = 0;
static constexpr int O_SLO = 16384;
static constexpr int O_WHI = 32768;
static constexpr int O_WLO = 35840;
static constexpr int O_TOT = 38912;

__global__ void __launch_bounds__(256, 2)
offset_mma_kernel(const float* __restrict__ x,
                  const float* __restrict__ bo) {
    extern __shared__ __align__(1024) char smem[];
    u32 sb = smem_u32(smem);

    int t    = threadIdx.x;
    int wid  = t >> 5;
    int lane = t & 31;
    int g    = lane >> 2;
    int tig  = lane & 3;

    int tile = blockIdx.x;
    int h = tile & 127;
    int b = tile >> 7;
    const float* xb = x + (size_t)b * Cs * HW;

    int spx   = t & 127;
    int cbase = (t >> 7) * 32;
    int m0    = wid * 16;

    // ldmatrix per-lane constants
    int lr  = lane & 7;
    int lmi = lane >> 3;
    u32 aRow = (u32)((m0 + (lmi & 1) * 8 + lr) * 128);
    u32 aKof = (u32)((lmi >> 1) * 16);
    u32 bRow = (u32)(((lmi >> 1) * 8 + lr) * 128);   // within 16-row n-pair
    u32 bKof = (u32)((lmi & 1) * 16);
    u32 b2Row = (u32)((16 + lr) * 128);              // n-tile 2 rows (x2; lanes 0-15 used)
    u32 b2Kof = (u32)((lmi & 1) * 16);

    float acc[3][4];
#pragma unroll
    for (int nt = 0; nt < 3; nt++)
#pragma unroll
        for (int j = 0; j < 4; j++) acc[nt][j] = 0.0f;

#pragma unroll 1
    for (int k = 0; k < 9; k++) {
        if (t < 192) {
            int n  = t >> 3;
            int c8 = t & 7;
            u32 dst = SMEM_SWIZZLE_128B((u32)(n * 128 + c8 * 16));
            *(uint4*)(smem + O_WHI + dst) =
                *(const uint4*)(g_wohi + k * NP * 64 + n * 64 + c8 * 8);
            *(uint4*)(smem + O_WLO + dst) =
                *(const uint4*)(g_wolo + k * NP * 64 + n * 64 + c8 * 8);
        }

        {
            int kh = k / 3, kw = k - kh * 3;
            int iy = h - 1 + kh;
            int ix = spx - 1 + kw;
            float vf = (iy >= 0 && iy < Hs && ix >= 0 && ix < Ws) ? 1.0f : 0.0f;
            int cy = min(max(iy, 0), Hs - 1);
            int cx = min(max(ix, 0), Ws - 1);
            const float* xp = xb + cy * Ws + cx;

#pragma unroll
            for (int gq = 0; gq < 4; gq++) {
                int c0 = cbase + gq * 8;
                const float* xc = xp + (size_t)c0 * HW;
                u32 hh[4], ll[4];
#pragma unroll
                for (int j2 = 0; j2 < 4; j2++) {
                    float se = __ldg(xc) * vf;              xc += HW;
                    float so = __ldg(xc) * vf;              xc += HW;
                    __nv_bfloat16 he, le, ho, lo2;
                    split_bf16(se, he, le);
                    split_bf16(so, ho, lo2);
                    hh[j2] = (u32)__bfloat16_as_ushort(he) |
                             ((u32)__bfloat16_as_ushort(ho) << 16);
                    ll[j2] = (u32)__bfloat16_as_ushort(le) |
                             ((u32)__bfloat16_as_ushort(lo2) << 16);
                }
                u32 off = SMEM_SWIZZLE_128B((u32)(spx * 128 + c0 * 2));
                *(uint4*)(smem + O_SHI + off) = make_uint4(hh[0], hh[1], hh[2], hh[3]);
                *(uint4*)(smem + O_SLO + off) = make_uint4(ll[0], ll[1], ll[2], ll[3]);
            }
        }
        __syncthreads();

#pragma unroll
        for (int ks = 0; ks < 4; ks++) {
            u32 kb = (u32)(ks * 32);
            u32 ah[4], al[4];
            ldsm_x4(ah, sb + O_SHI + SMEM_SWIZZLE_128B(aRow + kb + aKof));
            ldsm_x4(al, sb + O_SLO + SMEM_SWIZZLE_128B(aRow + kb + aKof));
            // n-tiles 0,1 via x4
            u32 bh[4], bl[4];
            ldsm_x4(bh, sb + O_WHI + SMEM_SWIZZLE_128B(bRow + kb + bKof));
            ldsm_x4(bl, sb + O_WLO + SMEM_SWIZZLE_128B(bRow + kb + bKof));
            hmma(acc[0], ah, bh);     hmma(acc[0], ah, bl);     hmma(acc[0], al, bh);
            hmma(acc[1], ah, bh + 2); hmma(acc[1], ah, bl + 2); hmma(acc[1], al, bh + 2);
            // n-tile 2 via x2
            u32 ch[2], cl[2];
            ldsm_x2(ch, sb + O_WHI + SMEM_SWIZZLE_128B(b2Row + kb + b2Kof));
            ldsm_x2(cl, sb + O_WLO + SMEM_SWIZZLE_128B(b2Row + kb + b2Kof));
            hmma(acc[2], ah, ch);     hmma(acc[2], ah, cl);     hmma(acc[2], al, ch);
        }
        __syncthreads();
    }

    float* O = (float*)smem;       // [24 n][132 m]
#pragma unroll
    for (int nt = 0; nt < 3; nt++) {
        int n = nt * 8 + tig * 2;
        int m = m0 + g;
        O[n * 132 + m]            = acc[nt][0];
        O[(n + 1) * 132 + m]      = acc[nt][1];
        O[n * 132 + m + 8]        = acc[nt][2];
        O[(n + 1) * 132 + m + 8]  = acc[nt][3];
    }
    __syncthreads();

    int Pbase = tile * 128;
    for (int i = t; i < 9 * 128; i += 256) {
        int k2 = i >> 7;
        int m  = i & 127;
        float dy = O[(2 * k2) * 132 + m]     + __ldg(bo + 2 * k2);
        float dx = O[(2 * k2 + 1) * 132 + m] + __ldg(bo + 2 * k2 + 1);
        g_off[k2 * 4 * HW + Pbase + m] = pack2(dy, dx);
    }
}

// ================= Kernel 2: deformable conv via mma.sync bf16x3 + ldmatrix =================
static constexpr int SM_SHI = 0;
static constexpr int SM_SLO = 16384;
static constexpr int SM_WHI = 32768;
static constexpr int SM_WLO = 40960;
static constexpr int SM_TOT = 49152;

__global__ void __launch_bounds__(256, 2)
deform_mma_kernel(const float* __restrict__ x,
                  const float* __restrict__ bd,
                  float* __restrict__ out) {
    extern __shared__ __align__(1024) char smem[];
    u32 sb = smem_u32(smem);

    int t    = threadIdx.x;
    int wid  = t >> 5;
    int lane = t & 31;
    int g    = lane >> 2;
    int tig  = lane & 3;

    int tile = blockIdx.x;
    int h = tile & 127;
    int b = tile >> 7;
    const float* xb = x + (size_t)b * Cs * HW;

    int spx   = t & 127;
    int cbase = (t >> 7) * 32;
    int P     = tile * 128 + spx;
    int m0    = wid * 16;

    // ldmatrix per-lane constants
    int lr  = lane & 7;
    int lmi = lane >> 3;
    u32 aRow = (u32)((m0 + (lmi & 1) * 8 + lr) * 128);
    u32 aKof = (u32)((lmi >> 1) * 16);
    u32 bRow = (u32)(((lmi >> 1) * 8 + lr) * 128);   // within 16-row n-pair
    u32 bKof = (u32)((lmi & 1) * 16);

    float acc[8][4];
#pragma unroll
    for (int nt = 0; nt < 8; nt++)
#pragma unroll
        for (int j = 0; j < 4; j++) acc[nt][j] = 0.0f;

#pragma unroll 1
    for (int k = 0; k < 9; k++) {
        for (int j = t; j < 512; j += 256) {
            int n  = j >> 3;
            int c8 = j & 7;
            u32 dst = SMEM_SWIZZLE_128B((u32)(n * 128 + c8 * 16));
            *(uint4*)(smem + SM_WHI + dst) =
                *(const uint4*)(g_whi + k * 4096 + n * 64 + c8 * 8);
            *(uint4*)(smem + SM_WLO + dst) =
                *(const uint4*)(g_wlo + k * 4096 + n * 64 + c8 * 8);
        }

        {
            int kh = k / 3, kw = k - kh * 3;
            float dlo, dhi;
            unpack2(g_off[k * 4 * HW + P], dlo, dhi);
            float py = (float)(h - 1 + kh) + dlo;
            float px = (float)(spx - 1 + kw) + dhi;
            float y0f = floorf(py), x0f = floorf(px);
            int y0 = (int)y0f, x0 = (int)x0f;
            int y1 = y0 + 1,   x1 = x0 + 1;
            float wy1 = py - y0f, wy0 = 1.0f - wy1;
            float wx1 = px - x0f, wx0 = 1.0f - wx1;
            float vy0 = (y0 >= 0 && y0 < Hs) ? 1.0f : 0.0f;
            float vy1 = (y1 >= 0 && y1 < Hs) ? 1.0f : 0.0f;
            float vx0 = (x0 >= 0 && x0 < Ws) ? 1.0f : 0.0f;
            float vx1 = (x1 >= 0 && x1 < Ws) ? 1.0f : 0.0f;
            float w00 = wy0 * wx0 * vy0 * vx0;
            float w01 = wy0 * wx1 * vy0 * vx1;
            float w10 = wy1 * wx0 * vy1 * vx0;
            float w11 = wy1 * wx1 * vy1 * vx1;
            int cy0 = min(max(y0, 0), Hs - 1), cy1 = min(max(y1, 0), Hs - 1);
            int cx0 = min(max(x0, 0), Ws - 1), cx1 = min(max(x1, 0), Ws - 1);
            int o00 = cy0 * Ws + cx0, o01 = cy0 * Ws + cx1;
            int o10 = cy1 * Ws + cx0, o11 = cy1 * Ws + cx1;

#pragma unroll
            for (int gq = 0; gq < 4; gq++) {
                int c0 = cbase + gq * 8;
                const float* xc = xb + (size_t)c0 * HW;
                float s[8];
#pragma unroll
                for (int j = 0; j < 8; j++) {
                    s[j] = fmaf(w00, __ldg(xc + o00),
                           fmaf(w01, __ldg(xc + o01),
                           fmaf(w10, __ldg(xc + o10), w11 * __ldg(xc + o11))));
                    xc += HW;
                }
                u32 hh[4], ll[4];
#pragma unroll
                for (int j2 = 0; j2 < 4; j2++) {
                    float se = s[2 * j2], so = s[2 * j2 + 1];
                    __nv_bfloat16 he, le, ho, lo2;
                    split_bf16(se, he, le);
                    split_bf16(so, ho, lo2);
                    hh[j2] = (u32)__bfloat16_as_ushort(he) |
                             ((u32)__bfloat16_as_ushort(ho) << 16);
                    ll[j2] = (u32)__bfloat16_as_ushort(le) |
                             ((u32)__bfloat16_as_ushort(lo2) << 16);
                }
                u32 off = SMEM_SWIZZLE_128B((u32)(spx * 128 + c0 * 2));
                *(uint4*)(smem + SM_SHI + off) = make_uint4(hh[0], hh[1], hh[2], hh[3]);
                *(uint4*)(smem + SM_SLO + off) = make_uint4(ll[0], ll[1], ll[2], ll[3]);
            }
        }
        __syncthreads();

#pragma unroll
        for (int ks = 0; ks < 4; ks++) {
            u32 kb = (u32)(ks * 32);
            u32 ah[4], al[4];
            ldsm_x4(ah, sb + SM_SHI + SMEM_SWIZZLE_128B(aRow + kb + aKof));
            ldsm_x4(al, sb + SM_SLO + SMEM_SWIZZLE_128B(aRow + kb + aKof));
#pragma unroll
            for (int p = 0; p < 4; p++) {
                u32 bh[4], bl[4];
                u32 boff = SMEM_SWIZZLE_128B((u32)(p * 2048) + bRow + kb + bKof);
                ldsm_x4(bh, sb + SM_WHI + boff);
                ldsm_x4(bl, sb + SM_WLO + boff);
                hmma(acc[2 * p],     ah, bh);     hmma(acc[2 * p],     ah, bl);
                hmma(acc[2 * p],     al, bh);
                hmma(acc[2 * p + 1], ah, bh + 2); hmma(acc[2 * p + 1], ah, bl + 2);
                hmma(acc[2 * p + 1], al, bh + 2);
            }
        }
        __syncthreads();
    }

    float* O = (float*)smem;       // [64 n][132 m]
#pragma unroll
    for (int nt = 0; nt < 8; nt++) {
        int n = nt * 8 + tig * 2;
        int m = m0 + g;
        O[n * 132 + m]            = acc[nt][0];
        O[(n + 1) * 132 + m]      = acc[nt][1];
        O[n * 132 + m + 8]        = acc[nt][2];
        O[(n + 1) * 132 + m + 8]  = acc[nt][3];
    }
    __syncthreads();

    float* ob = out + (size_t)b * Os * HW + h * 128;
    for (int i = t; i < 64 * 128; i += 256) {
        int o  = i >> 7;
        int w2 = i & 127;
        ob[(size_t)o * HW + w2] = O[o * 132 + w2] + __ldg(bd + o);
    }
}

// ---------------- harness entry ----------------
extern "C" void kernel_launch(void* const* d_in, const int* in_sizes, int n_in,
                              void* d_out, int out_size) {
    const float* x  = (const float*)d_in[0];   // [4,64,128,128]
    const float* wo = (const float*)d_in[1];   // [18,64,3,3]
    const float* bo = (const float*)d_in[2];   // [18]
    const float* wd = (const float*)d_in[3];   // [64,64,3,3]
    const float* bd = (const float*)d_in[4];   // [64]
    float* out = (float*)d_out;                // [4,64,128,128]

    cudaFuncSetAttribute(offset_mma_kernel,
                         cudaFuncAttributeMaxDynamicSharedMemorySize, O_TOT);
    cudaFuncSetAttribute(deform_mma_kernel,
                         cudaFuncAttributeMaxDynamicSharedMemorySize, SM_TOT);

    wsplit_kernel<<<198, 256>>>(wd, wo);
    offset_mma_kernel<<<512, 256, O_TOT>>>(x, bo);
    deform_mma_kernel<<<512, 256, SM_TOT>>>(x, bd, out);
}

// round 12
// speedup vs baseline: 1.2015x; 1.0282x over previous
#include <cuda_runtime.h>
#include <cuda_bf16.h>
#include <math.h>

#define Hs   128
#define Ws   128
#define Cs   64
#define Os   64
#define HW   16384
#define Q    576          // Cs * 9
#define NP   24           // padded N for offset conv

typedef unsigned long long u64;
typedef unsigned int u32;

// bf16-split deform weights: [k][o][c]
__device__ __align__(16) __nv_bfloat16 g_whi[9 * 64 * 64];
__device__ __align__(16) __nv_bfloat16 g_wlo[9 * 64 * 64];
// bf16-split offset-conv weights: [k][n(24)][c]
__device__ __align__(16) __nv_bfloat16 g_wohi[9 * NP * 64];
__device__ __align__(16) __nv_bfloat16 g_wolo[9 * NP * 64];

// ---------------- helpers ----------------
__device__ __forceinline__ u64 pack2(float lo, float hi) {
    u64 r;
    asm("mov.b64 %0, {%1, %2};" : "=l"(r) : "f"(lo), "f"(hi));
    return r;
}
__device__ __forceinline__ void unpack2(u64 v, float& lo, float& hi) {
    asm("mov.b64 {%0, %1}, %2;" : "=f"(lo), "=f"(hi) : "l"(v));
}
__device__ __forceinline__ u32 smem_u32(const void* p) {
    u32 a;
    asm("{ .reg .u64 t; cvta.to.shared.u64 t, %1; cvt.u32.u64 %0, t; }"
        : "=r"(a) : "l"(p));
    return a;
}

#define SMEM_SWIZZLE_128B(o) ((o) ^ (((o) >> 3) & 0x70))

__device__ __forceinline__ void hmma(float* d, const u32* a, const u32* b) {
    asm volatile(
        "mma.sync.aligned.m16n8k16.row.col.f32.bf16.bf16.f32 "
        "{%0,%1,%2,%3}, {%4,%5,%6,%7}, {%8,%9}, {%0,%1,%2,%3};"
        : "+f"(d[0]), "+f"(d[1]), "+f"(d[2]), "+f"(d[3])
        : "r"(a[0]), "r"(a[1]), "r"(a[2]), "r"(a[3]), "r"(b[0]), "r"(b[1]));
}

__device__ __forceinline__ void ldsm_x4(u32* d, u32 addr) {
    asm volatile("ldmatrix.sync.aligned.m8n8.x4.shared.b16 {%0,%1,%2,%3}, [%4];"
        : "=r"(d[0]), "=r"(d[1]), "=r"(d[2]), "=r"(d[3]) : "r"(addr));
}
__device__ __forceinline__ void ldsm_x2(u32* d, u32 addr) {
    asm volatile("ldmatrix.sync.aligned.m8n8.x2.shared.b16 {%0,%1}, [%2];"
        : "=r"(d[0]), "=r"(d[1]) : "r"(addr));
}

__device__ __forceinline__ void split_bf16(float v, __nv_bfloat16& h, __nv_bfloat16& l) {
    h = __float2bfloat16(v);
    l = __float2bfloat16(v - __bfloat162float(h));
}

// ================= Kernel 0: split both weight sets to bf16 hi/lo =================
__global__ void wsplit_kernel(const float* __restrict__ wd,
                              const float* __restrict__ wo) {
    int i = blockIdx.x * 256 + threadIdx.x;
    if (i < 9 * 64 * 64) {
        int k = i >> 12;
        int r = i & 4095;
        int o = r >> 6;
        int c = r & 63;
        float v = wd[o * Q + c * 9 + k];
        __nv_bfloat16 h, l;
        split_bf16(v, h, l);
        g_whi[i] = h;
        g_wlo[i] = l;
    } else if (i < 9 * 64 * 64 + 9 * NP * 64) {
        int j = i - 9 * 64 * 64;
        int k = j / (NP * 64);
        int r = j - k * (NP * 64);
        int n = r >> 6;
        int c = r & 63;
        float v = (n < 18) ? wo[n * Q + c * 9 + k] : 0.0f;
        __nv_bfloat16 h, l;
        split_bf16(v, h, l);
        g_wohi[j] = h;
        g_wolo[j] = l;
    }
}

// ================= Fused kernel: offset conv + deformable conv, one CTA per row =================
// SMEM layout (58368 B):
//   S_hi  @0      (16384)   sampled A tiles (both phases)
//   S_lo  @16384  (16384)
//   W_hi  @32768  (8192)    weight chunk (both phases; offset uses 3072 of it)
//   W_lo  @40960  (8192)
//   OFF   @49152  (9216)    u64 offbuf[9][128] = per-pixel (dy,dx), phase 1 -> phase 2
// Transpose buffers O[.][132] overlay S regions between syncs.
static constexpr int SM_SHI = 0;
static constexpr int SM_SLO = 16384;
static constexpr int SM_WHI = 32768;
static constexpr int SM_WLO = 40960;
static constexpr int SM_OFF = 49152;
static constexpr int SM_TOT = 58368;

__global__ void __launch_bounds__(256, 2)
fused_deform_kernel(const float* __restrict__ x,
                    const float* __restrict__ bo,
                    const float* __restrict__ bd,
                    float* __restrict__ out) {
    extern __shared__ __align__(1024) char smem[];
    u32 sb = smem_u32(smem);
    u64* offbuf = (u64*)(smem + SM_OFF);     // [9][128]

    int t    = threadIdx.x;
    int wid  = t >> 5;
    int lane = t & 31;
    int g    = lane >> 2;
    int tig  = lane & 3;

    int tile = blockIdx.x;
    int h = tile & 127;
    int b = tile >> 7;
    const float* xb = x + (size_t)b * Cs * HW;

    int spx   = t & 127;
    int cbase = (t >> 7) * 32;
    int m0    = wid * 16;

    // ldmatrix per-lane constants
    int lr  = lane & 7;
    int lmi = lane >> 3;
    u32 aRow = (u32)((m0 + (lmi & 1) * 8 + lr) * 128);
    u32 aKof = (u32)((lmi >> 1) * 16);
    u32 bRow = (u32)(((lmi >> 1) * 8 + lr) * 128);
    u32 bKof = (u32)((lmi & 1) * 16);
    u32 b2Row = (u32)((16 + lr) * 128);
    u32 b2Kof = (u32)((lmi & 1) * 16);

    // ============ PHASE 1: offset conv (M=128, N=24, K=576) ============
    {
        float acc[3][4];
#pragma unroll
        for (int nt = 0; nt < 3; nt++)
#pragma unroll
            for (int j = 0; j < 4; j++) acc[nt][j] = 0.0f;

#pragma unroll 1
        for (int k = 0; k < 9; k++) {
            if (t < 192) {
                int n  = t >> 3;
                int c8 = t & 7;
                u32 dst = SMEM_SWIZZLE_128B((u32)(n * 128 + c8 * 16));
                *(uint4*)(smem + SM_WHI + dst) =
                    *(const uint4*)(g_wohi + k * NP * 64 + n * 64 + c8 * 8);
                *(uint4*)(smem + SM_WLO + dst) =
                    *(const uint4*)(g_wolo + k * NP * 64 + n * 64 + c8 * 8);
            }

            {
                int kh = k / 3, kw = k - kh * 3;
                int iy = h - 1 + kh;
                int ix = spx - 1 + kw;
                float vf = (iy >= 0 && iy < Hs && ix >= 0 && ix < Ws) ? 1.0f : 0.0f;
                int cy = min(max(iy, 0), Hs - 1);
                int cx = min(max(ix, 0), Ws - 1);
                const float* xp = xb + cy * Ws + cx;

#pragma unroll
                for (int gq = 0; gq < 4; gq++) {
                    int c0 = cbase + gq * 8;
                    const float* xc = xp + (size_t)c0 * HW;
                    u32 hh[4], ll[4];
#pragma unroll
                    for (int j2 = 0; j2 < 4; j2++) {
                        float se = __ldg(xc) * vf;              xc += HW;
                        float so = __ldg(xc) * vf;              xc += HW;
                        __nv_bfloat16 he, le, ho, lo2;
                        split_bf16(se, he, le);
                        split_bf16(so, ho, lo2);
                        hh[j2] = (u32)__bfloat16_as_ushort(he) |
                                 ((u32)__bfloat16_as_ushort(ho) << 16);
                        ll[j2] = (u32)__bfloat16_as_ushort(le) |
                                 ((u32)__bfloat16_as_ushort(lo2) << 16);
                    }
                    u32 off = SMEM_SWIZZLE_128B((u32)(spx * 128 + c0 * 2));
                    *(uint4*)(smem + SM_SHI + off) = make_uint4(hh[0], hh[1], hh[2], hh[3]);
                    *(uint4*)(smem + SM_SLO + off) = make_uint4(ll[0], ll[1], ll[2], ll[3]);
                }
            }
            __syncthreads();

#pragma unroll
            for (int ks = 0; ks < 4; ks++) {
                u32 kb = (u32)(ks * 32);
                u32 ah[4], al[4];
                ldsm_x4(ah, sb + SM_SHI + SMEM_SWIZZLE_128B(aRow + kb + aKof));
                ldsm_x4(al, sb + SM_SLO + SMEM_SWIZZLE_128B(aRow + kb + aKof));
                u32 bh[4], bl[4];
                ldsm_x4(bh, sb + SM_WHI + SMEM_SWIZZLE_128B(bRow + kb + bKof));
                ldsm_x4(bl, sb + SM_WLO + SMEM_SWIZZLE_128B(bRow + kb + bKof));
                hmma(acc[0], ah, bh);     hmma(acc[0], ah, bl);     hmma(acc[0], al, bh);
                hmma(acc[1], ah, bh + 2); hmma(acc[1], ah, bl + 2); hmma(acc[1], al, bh + 2);
                u32 ch[2], cl[2];
                ldsm_x2(ch, sb + SM_WHI + SMEM_SWIZZLE_128B(b2Row + kb + b2Kof));
                ldsm_x2(cl, sb + SM_WLO + SMEM_SWIZZLE_128B(b2Row + kb + b2Kof));
                hmma(acc[2], ah, ch);     hmma(acc[2], ah, cl);     hmma(acc[2], al, ch);
            }
            __syncthreads();
        }

        // transpose via smem (overlay S region), write (dy,dx) pairs to offbuf
        float* O = (float*)smem;       // [24 n][132 m]
#pragma unroll
        for (int nt = 0; nt < 3; nt++) {
            int n = nt * 8 + tig * 2;
            int m = m0 + g;
            O[n * 132 + m]            = acc[nt][0];
            O[(n + 1) * 132 + m]      = acc[nt][1];
            O[n * 132 + m + 8]        = acc[nt][2];
            O[(n + 1) * 132 + m + 8]  = acc[nt][3];
        }
        __syncthreads();

        for (int i = t; i < 9 * 128; i += 256) {
            int k2 = i >> 7;
            int m  = i & 127;
            float dy = O[(2 * k2) * 132 + m]     + __ldg(bo + 2 * k2);
            float dx = O[(2 * k2 + 1) * 132 + m] + __ldg(bo + 2 * k2 + 1);
            offbuf[k2 * 128 + m] = pack2(dy, dx);
        }
        __syncthreads();   // offbuf ready; O region free for phase 2
    }

    // ============ PHASE 2: deformable conv (M=128, N=64, K=576) ============
    {
        float acc[8][4];
#pragma unroll
        for (int nt = 0; nt < 8; nt++)
#pragma unroll
            for (int j = 0; j < 4; j++) acc[nt][j] = 0.0f;

#pragma unroll 1
        for (int k = 0; k < 9; k++) {
            for (int j = t; j < 512; j += 256) {
                int n  = j >> 3;
                int c8 = j & 7;
                u32 dst = SMEM_SWIZZLE_128B((u32)(n * 128 + c8 * 16));
                *(uint4*)(smem + SM_WHI + dst) =
                    *(const uint4*)(g_whi + k * 4096 + n * 64 + c8 * 8);
                *(uint4*)(smem + SM_WLO + dst) =
                    *(const uint4*)(g_wlo + k * 4096 + n * 64 + c8 * 8);
            }

            {
                int kh = k / 3, kw = k - kh * 3;
                float dlo, dhi;
                unpack2(offbuf[k * 128 + spx], dlo, dhi);
                float py = (float)(h - 1 + kh) + dlo;
                float px = (float)(spx - 1 + kw) + dhi;
                float y0f = floorf(py), x0f = floorf(px);
                int y0 = (int)y0f, x0 = (int)x0f;
                int y1 = y0 + 1,   x1 = x0 + 1;
                float wy1 = py - y0f, wy0 = 1.0f - wy1;
                float wx1 = px - x0f, wx0 = 1.0f - wx1;
                float vy0 = (y0 >= 0 && y0 < Hs) ? 1.0f : 0.0f;
                float vy1 = (y1 >= 0 && y1 < Hs) ? 1.0f : 0.0f;
                float vx0 = (x0 >= 0 && x0 < Ws) ? 1.0f : 0.0f;
                float vx1 = (x1 >= 0 && x1 < Ws) ? 1.0f : 0.0f;
                float w00 = wy0 * wx0 * vy0 * vx0;
                float w01 = wy0 * wx1 * vy0 * vx1;
                float w10 = wy1 * wx0 * vy1 * vx0;
                float w11 = wy1 * wx1 * vy1 * vx1;
                int cy0 = min(max(y0, 0), Hs - 1), cy1 = min(max(y1, 0), Hs - 1);
                int cx0 = min(max(x0, 0), Ws - 1), cx1 = min(max(x1, 0), Ws - 1);
                int o00 = cy0 * Ws + cx0, o01 = cy0 * Ws + cx1;
                int o10 = cy1 * Ws + cx0, o11 = cy1 * Ws + cx1;

#pragma unroll
                for (int gq = 0; gq < 4; gq++) {
                    int c0 = cbase + gq * 8;
                    const float* xc = xb + (size_t)c0 * HW;
                    float s[8];
#pragma unroll
                    for (int j = 0; j < 8; j++) {
                        s[j] = fmaf(w00, __ldg(xc + o00),
                               fmaf(w01, __ldg(xc + o01),
                               fmaf(w10, __ldg(xc + o10), w11 * __ldg(xc + o11))));
                        xc += HW;
                    }
                    u32 hh[4], ll[4];
#pragma unroll
                    for (int j2 = 0; j2 < 4; j2++) {
                        float se = s[2 * j2], so = s[2 * j2 + 1];
                        __nv_bfloat16 he, le, ho, lo2;
                        split_bf16(se, he, le);
                        split_bf16(so, ho, lo2);
                        hh[j2] = (u32)__bfloat16_as_ushort(he) |
                                 ((u32)__bfloat16_as_ushort(ho) << 16);
                        ll[j2] = (u32)__bfloat16_as_ushort(le) |
                                 ((u32)__bfloat16_as_ushort(lo2) << 16);
                    }
                    u32 off = SMEM_SWIZZLE_128B((u32)(spx * 128 + c0 * 2));
                    *(uint4*)(smem + SM_SHI + off) = make_uint4(hh[0], hh[1], hh[2], hh[3]);
                    *(uint4*)(smem + SM_SLO + off) = make_uint4(ll[0], ll[1], ll[2], ll[3]);
                }
            }
            __syncthreads();

#pragma unroll
            for (int ks = 0; ks < 4; ks++) {
                u32 kb = (u32)(ks * 32);
                u32 ah[4], al[4];
                ldsm_x4(ah, sb + SM_SHI + SMEM_SWIZZLE_128B(aRow + kb + aKof));
                ldsm_x4(al, sb + SM_SLO + SMEM_SWIZZLE_128B(aRow + kb + aKof));
#pragma unroll
                for (int p = 0; p < 4; p++) {
                    u32 bh[4], bl[4];
                    u32 boff = SMEM_SWIZZLE_128B((u32)(p * 2048) + bRow + kb + bKof);
                    ldsm_x4(bh, sb + SM_WHI + boff);
                    ldsm_x4(bl, sb + SM_WLO + boff);
                    hmma(acc[2 * p],     ah, bh);     hmma(acc[2 * p],     ah, bl);
                    hmma(acc[2 * p],     al, bh);
                    hmma(acc[2 * p + 1], ah, bh + 2); hmma(acc[2 * p + 1], ah, bl + 2);
                    hmma(acc[2 * p + 1], al, bh + 2);
                }
            }
            __syncthreads();
        }

        float* O = (float*)smem;       // [64 n][132 m]
#pragma unroll
        for (int nt = 0; nt < 8; nt++) {
            int n = nt * 8 + tig * 2;
            int m = m0 + g;
            O[n * 132 + m]            = acc[nt][0];
            O[(n + 1) * 132 + m]      = acc[nt][1];
            O[n * 132 + m + 8]        = acc[nt][2];
            O[(n + 1) * 132 + m + 8]  = acc[nt][3];
        }
        __syncthreads();

        float* ob = out + (size_t)b * Os * HW + h * 128;
        for (int i = t; i < 64 * 128; i += 256) {
            int o  = i >> 7;
            int w2 = i & 127;
            ob[(size_t)o * HW + w2] = O[o * 132 + w2] + __ldg(bd + o);
        }
    }
}

// ---------------- harness entry ----------------
extern "C" void kernel_launch(void* const* d_in, const int* in_sizes, int n_in,
                              void* d_out, int out_size) {
    const float* x  = (const float*)d_in[0];   // [4,64,128,128]
    const float* wo = (const float*)d_in[1];   // [18,64,3,3]
    const float* bo = (const float*)d_in[2];   // [18]
    const float* wd = (const float*)d_in[3];   // [64,64,3,3]
    const float* bd = (const float*)d_in[4];   // [64]
    float* out = (float*)d_out;                // [4,64,128,128]

    cudaFuncSetAttribute(fused_deform_kernel,
                         cudaFuncAttributeMaxDynamicSharedMemorySize, SM_TOT);

    wsplit_kernel<<<198, 256>>>(wd, wo);
    fused_deform_kernel<<<512, 256, SM_TOT>>>(x, bo, bd, out);
}

// round 13
// speedup vs baseline: 1.2038x; 1.0019x over previous
#include <cuda_runtime.h>
#include <cuda_bf16.h>
#include <math.h>

#define Hs   128
#define Ws   128
#define Cs   64
#define Os   64
#define HW   16384
#define Q    576          // Cs * 9
#define NP   24           // padded N for offset conv

typedef unsigned long long u64;
typedef unsigned int u32;

// channel-last transpose of x: [b][y][x][c]
__device__ __align__(16) float g_xt[4 * HW * 64];
// bf16-split deform weights: [k][o][c]
__device__ __align__(16) __nv_bfloat16 g_whi[9 * 64 * 64];
__device__ __align__(16) __nv_bfloat16 g_wlo[9 * 64 * 64];
// bf16-split offset-conv weights: [k][n(24)][c]
__device__ __align__(16) __nv_bfloat16 g_wohi[9 * NP * 64];
__device__ __align__(16) __nv_bfloat16 g_wolo[9 * NP * 64];

// ---------------- helpers ----------------
__device__ __forceinline__ u64 pack2(float lo, float hi) {
    u64 r;
    asm("mov.b64 %0, {%1, %2};" : "=l"(r) : "f"(lo), "f"(hi));
    return r;
}
__device__ __forceinline__ void unpack2(u64 v, float& lo, float& hi) {
    asm("mov.b64 {%0, %1}, %2;" : "=f"(lo), "=f"(hi) : "l"(v));
}
__device__ __forceinline__ u64 pack64(u32 a, u32 b) {
    return (u64)a | ((u64)b << 32);
}
__device__ __forceinline__ u32 smem_u32(const void* p) {
    u32 a;
    asm("{ .reg .u64 t; cvta.to.shared.u64 t, %1; cvt.u32.u64 %0, t; }"
        : "=r"(a) : "l"(p));
    return a;
}

#define SMEM_SWIZZLE_128B(o) ((o) ^ (((o) >> 3) & 0x70))

__device__ __forceinline__ void hmma(float* d, const u32* a, const u32* b) {
    asm volatile(
        "mma.sync.aligned.m16n8k16.row.col.f32.bf16.bf16.f32 "
        "{%0,%1,%2,%3}, {%4,%5,%6,%7}, {%8,%9}, {%0,%1,%2,%3};"
        : "+f"(d[0]), "+f"(d[1]), "+f"(d[2]), "+f"(d[3])
        : "r"(a[0]), "r"(a[1]), "r"(a[2]), "r"(a[3]), "r"(b[0]), "r"(b[1]));
}

__device__ __forceinline__ void ldsm_x4(u32* d, u32 addr) {
    asm volatile("ldmatrix.sync.aligned.m8n8.x4.shared.b16 {%0,%1,%2,%3}, [%4];"
        : "=r"(d[0]), "=r"(d[1]), "=r"(d[2]), "=r"(d[3]) : "r"(addr));
}
__device__ __forceinline__ void ldsm_x2(u32* d, u32 addr) {
    asm volatile("ldmatrix.sync.aligned.m8n8.x2.shared.b16 {%0,%1}, [%2];"
        : "=r"(d[0]), "=r"(d[1]) : "r"(addr));
}

__device__ __forceinline__ void split_bf16(float v, __nv_bfloat16& h, __nv_bfloat16& l) {
    h = __float2bfloat16(v);
    l = __float2bfloat16(v - __bfloat162float(h));
}
__device__ __forceinline__ void split2(float se, float so, u32& hh, u32& ll) {
    __nv_bfloat16 he, le, ho, lo2;
    split_bf16(se, he, le);
    split_bf16(so, ho, lo2);
    hh = (u32)__bfloat16_as_ushort(he) | ((u32)__bfloat16_as_ushort(ho) << 16);
    ll = (u32)__bfloat16_as_ushort(le) | ((u32)__bfloat16_as_ushort(lo2) << 16);
}

// ================= Kernel A: NCHW -> NHWC transpose of x =================
__global__ void __launch_bounds__(256)
transpose_kernel(const float* __restrict__ x) {
    __shared__ float tile[64 * 129];
    int row = blockIdx.x;               // b*128 + y
    int y = row & 127, b = row >> 7;
    const float* xb = x + (size_t)b * Cs * HW + y * Ws;
    int t = threadIdx.x;
    int w0 = t & 127, c0 = t >> 7;
#pragma unroll
    for (int i = 0; i < 32; i++) {
        int c = c0 + i * 2;
        tile[c * 129 + w0] = __ldg(xb + (size_t)c * HW + w0);
    }
    __syncthreads();
    float* dst = g_xt + (size_t)row * 128 * 64;
#pragma unroll
    for (int i = 0; i < 32; i++) {
        int idx = t + i * 256;          // idx = w*64 + c
        dst[idx] = tile[(idx & 63) * 129 + (idx >> 6)];
    }
}

// ================= Kernel 0: split both weight sets to bf16 hi/lo =================
__global__ void wsplit_kernel(const float* __restrict__ wd,
                              const float* __restrict__ wo) {
    int i = blockIdx.x * 256 + threadIdx.x;
    if (i < 9 * 64 * 64) {
        int k = i >> 12;
        int r = i & 4095;
        int o = r >> 6;
        int c = r & 63;
        float v = wd[o * Q + c * 9 + k];
        __nv_bfloat16 h, l;
        split_bf16(v, h, l);
        g_whi[i] = h;
        g_wlo[i] = l;
    } else if (i < 9 * 64 * 64 + 9 * NP * 64) {
        int j = i - 9 * 64 * 64;
        int k = j / (NP * 64);
        int r = j - k * (NP * 64);
        int n = r >> 6;
        int c = r & 63;
        float v = (n < 18) ? wo[n * Q + c * 9 + k] : 0.0f;
        __nv_bfloat16 h, l;
        split_bf16(v, h, l);
        g_wohi[j] = h;
        g_wolo[j] = l;
    }
}

// ================= Fused kernel: offset conv + deformable conv =================
static constexpr int SM_SHI = 0;
static constexpr int SM_SLO = 16384;
static constexpr int SM_WHI = 32768;
static constexpr int SM_WLO = 40960;
static constexpr int SM_OFF = 49152;
static constexpr int SM_TOT = 58368;

__global__ void __launch_bounds__(256, 2)
fused_deform_kernel(const float* __restrict__ bo,
                    const float* __restrict__ bd,
                    float* __restrict__ out) {
    extern __shared__ __align__(1024) char smem[];
    u32 sb = smem_u32(smem);
    u64* offbuf = (u64*)(smem + SM_OFF);     // [9][128]

    int t    = threadIdx.x;
    int wid  = t >> 5;
    int lane = t & 31;
    int g    = lane >> 2;
    int tig  = lane & 3;

    int tile = blockIdx.x;
    int h = tile & 127;
    int b = tile >> 7;
    const float* xt = g_xt + (size_t)b * HW * 64;   // [y][x][c]

    int m0 = wid * 16;
    int p0 = t >> 4;          // sampler pixel base (0..15)
    int q4 = (t & 15) * 4;    // channel quad -> channel index

    int lr  = lane & 7;
    int lmi = lane >> 3;
    u32 aRow = (u32)((m0 + (lmi & 1) * 8 + lr) * 128);
    u32 aKof = (u32)((lmi >> 1) * 16);
    u32 bRow = (u32)(((lmi >> 1) * 8 + lr) * 128);
    u32 bKof = (u32)((lmi & 1) * 16);
    u32 b2Row = (u32)((16 + lr) * 128);
    u32 b2Kof = (u32)((lmi & 1) * 16);

    // ============ PHASE 1: offset conv (M=128, N=24, K=576) ============
    {
        float acc[3][4];
#pragma unroll
        for (int nt = 0; nt < 3; nt++)
#pragma unroll
            for (int j = 0; j < 4; j++) acc[nt][j] = 0.0f;

#pragma unroll 1
        for (int k = 0; k < 9; k++) {
            if (t < 192) {
                int n  = t >> 3;
                int c8 = t & 7;
                u32 dst = SMEM_SWIZZLE_128B((u32)(n * 128 + c8 * 16));
                *(uint4*)(smem + SM_WHI + dst) =
                    *(const uint4*)(g_wohi + k * NP * 64 + n * 64 + c8 * 8);
                *(uint4*)(smem + SM_WLO + dst) =
                    *(const uint4*)(g_wolo + k * NP * 64 + n * 64 + c8 * 8);
            }

            {
                int kh = k / 3, kw = k - kh * 3;
                int iy = h - 1 + kh;
                bool yok = (iy >= 0 && iy < Hs);
                int cy = min(max(iy, 0), Hs - 1);
                const float* xrow = xt + (size_t)cy * 128 * 64;
#pragma unroll
                for (int it = 0; it < 8; it++) {
                    int p = p0 + it * 16;
                    int ix = p - 1 + kw;
                    float vf = (yok && ix >= 0 && ix < Ws) ? 1.0f : 0.0f;
                    int cx = min(max(ix, 0), Ws - 1);
                    float4 v = *(const float4*)(xrow + cx * 64 + q4);
                    u32 hh0, ll0, hh1, ll1;
                    split2(v.x * vf, v.y * vf, hh0, ll0);
                    split2(v.z * vf, v.w * vf, hh1, ll1);
                    u32 off = SMEM_SWIZZLE_128B((u32)(p * 128 + q4 * 2));
                    *(u64*)(smem + SM_SHI + off) = pack64(hh0, hh1);
                    *(u64*)(smem + SM_SLO + off) = pack64(ll0, ll1);
                }
            }
            __syncthreads();

#pragma unroll
            for (int ks = 0; ks < 4; ks++) {
                u32 kb = (u32)(ks * 32);
                u32 ah[4], al[4];
                ldsm_x4(ah, sb + SM_SHI + SMEM_SWIZZLE_128B(aRow + kb + aKof));
                ldsm_x4(al, sb + SM_SLO + SMEM_SWIZZLE_128B(aRow + kb + aKof));
                u32 bh[4], bl[4];
                ldsm_x4(bh, sb + SM_WHI + SMEM_SWIZZLE_128B(bRow + kb + bKof));
                ldsm_x4(bl, sb + SM_WLO + SMEM_SWIZZLE_128B(bRow + kb + bKof));
                hmma(acc[0], ah, bh);     hmma(acc[0], ah, bl);     hmma(acc[0], al, bh);
                hmma(acc[1], ah, bh + 2); hmma(acc[1], ah, bl + 2); hmma(acc[1], al, bh + 2);
                u32 ch[2], cl[2];
                ldsm_x2(ch, sb + SM_WHI + SMEM_SWIZZLE_128B(b2Row + kb + b2Kof));
                ldsm_x2(cl, sb + SM_WLO + SMEM_SWIZZLE_128B(b2Row + kb + b2Kof));
                hmma(acc[2], ah, ch);     hmma(acc[2], ah, cl);     hmma(acc[2], al, ch);
            }
            __syncthreads();
        }

        float* O = (float*)smem;       // [24 n][132 m]
#pragma unroll
        for (int nt = 0; nt < 3; nt++) {
            int n = nt * 8 + tig * 2;
            int m = m0 + g;
            O[n * 132 + m]            = acc[nt][0];
            O[(n + 1) * 132 + m]      = acc[nt][1];
            O[n * 132 + m + 8]        = acc[nt][2];
            O[(n + 1) * 132 + m + 8]  = acc[nt][3];
        }
        __syncthreads();

        for (int i = t; i < 9 * 128; i += 256) {
            int k2 = i >> 7;
            int m  = i & 127;
            float dy = O[(2 * k2) * 132 + m]     + __ldg(bo + 2 * k2);
            float dx = O[(2 * k2 + 1) * 132 + m] + __ldg(bo + 2 * k2 + 1);
            offbuf[k2 * 128 + m] = pack2(dy, dx);
        }
        __syncthreads();
    }

    // ============ PHASE 2: deformable conv (M=128, N=64, K=576) ============
    {
        float acc[8][4];
#pragma unroll
        for (int nt = 0; nt < 8; nt++)
#pragma unroll
            for (int j = 0; j < 4; j++) acc[nt][j] = 0.0f;

#pragma unroll 1
        for (int k = 0; k < 9; k++) {
            for (int j = t; j < 512; j += 256) {
                int n  = j >> 3;
                int c8 = j & 7;
                u32 dst = SMEM_SWIZZLE_128B((u32)(n * 128 + c8 * 16));
                *(uint4*)(smem + SM_WHI + dst) =
                    *(const uint4*)(g_whi + k * 4096 + n * 64 + c8 * 8);
                *(uint4*)(smem + SM_WLO + dst) =
                    *(const uint4*)(g_wlo + k * 4096 + n * 64 + c8 * 8);
            }

            {
                int kh = k / 3, kw = k - kh * 3;
                float hbase = (float)(h - 1 + kh);
#pragma unroll
                for (int it = 0; it < 8; it++) {
                    int p = p0 + it * 16;
                    float dlo, dhi;
                    unpack2(offbuf[k * 128 + p], dlo, dhi);
                    float py = hbase + dlo;
                    float px = (float)(p - 1 + kw) + dhi;
                    float y0f = floorf(py), x0f = floorf(px);
                    int y0 = (int)y0f, x0 = (int)x0f;
                    int y1 = y0 + 1,   x1 = x0 + 1;
                    float wy1 = py - y0f, wy0 = 1.0f - wy1;
                    float wx1 = px - x0f, wx0 = 1.0f - wx1;
                    float vy0 = (y0 >= 0 && y0 < Hs) ? 1.0f : 0.0f;
                    float vy1 = (y1 >= 0 && y1 < Hs) ? 1.0f : 0.0f;
                    float vx0 = (x0 >= 0 && x0 < Ws) ? 1.0f : 0.0f;
                    float vx1 = (x1 >= 0 && x1 < Ws) ? 1.0f : 0.0f;
                    float w00 = wy0 * wx0 * vy0 * vx0;
                    float w01 = wy0 * wx1 * vy0 * vx1;
                    float w10 = wy1 * wx0 * vy1 * vx0;
                    float w11 = wy1 * wx1 * vy1 * vx1;
                    int cy0 = min(max(y0, 0), Hs - 1), cy1 = min(max(y1, 0), Hs - 1);
                    int cx0 = min(max(x0, 0), Ws - 1), cx1 = min(max(x1, 0), Ws - 1);
                    const float* r0p = xt + (size_t)(cy0 * 128) * 64 + q4;
                    const float* r1p = xt + (size_t)(cy1 * 128) * 64 + q4;
                    float4 t00 = *(const float4*)(r0p + cx0 * 64);
                    float4 t01 = *(const float4*)(r0p + cx1 * 64);
                    float4 t10 = *(const float4*)(r1p + cx0 * 64);
                    float4 t11 = *(const float4*)(r1p + cx1 * 64);
                    float s0 = fmaf(w00, t00.x, fmaf(w01, t01.x, fmaf(w10, t10.x, w11 * t11.x)));
                    float s1 = fmaf(w00, t00.y, fmaf(w01, t01.y, fmaf(w10, t10.y, w11 * t11.y)));
                    float s2 = fmaf(w00, t00.z, fmaf(w01, t01.z, fmaf(w10, t10.z, w11 * t11.z)));
                    float s3 = fmaf(w00, t00.w, fmaf(w01, t01.w, fmaf(w10, t10.w, w11 * t11.w)));
                    u32 hh0, ll0, hh1, ll1;
                    split2(s0, s1, hh0, ll0);
                    split2(s2, s3, hh1, ll1);
                    u32 off = SMEM_SWIZZLE_128B((u32)(p * 128 + q4 * 2));
                    *(u64*)(smem + SM_SHI + off) = pack64(hh0, hh1);
                    *(u64*)(smem + SM_SLO + off) = pack64(ll0, ll1);
                }
            }
            __syncthreads();

#pragma unroll
            for (int ks = 0; ks < 4; ks++) {
                u32 kb = (u32)(ks * 32);
                u32 ah[4], al[4];
                ldsm_x4(ah, sb + SM_SHI + SMEM_SWIZZLE_128B(aRow + kb + aKof));
                ldsm_x4(al, sb + SM_SLO + SMEM_SWIZZLE_128B(aRow + kb + aKof));
#pragma unroll
                for (int p = 0; p < 4; p++) {
                    u32 bh[4], bl[4];
                    u32 boff = SMEM_SWIZZLE_128B((u32)(p * 2048) + bRow + kb + bKof);
                    ldsm_x4(bh, sb + SM_WHI + boff);
                    ldsm_x4(bl, sb + SM_WLO + boff);
                    hmma(acc[2 * p],     ah, bh);     hmma(acc[2 * p],     ah, bl);
                    hmma(acc[2 * p],     al, bh);
                    hmma(acc[2 * p + 1], ah, bh + 2); hmma(acc[2 * p + 1], ah, bl + 2);
                    hmma(acc[2 * p + 1], al, bh + 2);
                }
            }
            __syncthreads();
        }

        float* O = (float*)smem;       // [64 n][132 m]
#pragma unroll
        for (int nt = 0; nt < 8; nt++) {
            int n = nt * 8 + tig * 2;
            int m = m0 + g;
            O[n * 132 + m]            = acc[nt][0];
            O[(n + 1) * 132 + m]      = acc[nt][1];
            O[n * 132 + m + 8]        = acc[nt][2];
            O[(n + 1) * 132 + m + 8]  = acc[nt][3];
        }
        __syncthreads();

        float* ob = out + (size_t)b * Os * HW + h * 128;
        for (int i = t; i < 64 * 128; i += 256) {
            int o  = i >> 7;
            int w2 = i & 127;
            ob[(size_t)o * HW + w2] = O[o * 132 + w2] + __ldg(bd + o);
        }
    }
}

// ---------------- harness entry ----------------
extern "C" void kernel_launch(void* const* d_in, const int* in_sizes, int n_in,
                              void* d_out, int out_size) {
    const float* x  = (const float*)d_in[0];   // [4,64,128,128]
    const float* wo = (const float*)d_in[1];   // [18,64,3,3]
    const float* bo = (const float*)d_in[2];   // [18]
    const float* wd = (const float*)d_in[3];   // [64,64,3,3]
    const float* bd = (const float*)d_in[4];   // [64]
    float* out = (float*)d_out;                // [4,64,128,128]

    cudaFuncSetAttribute(fused_deform_kernel,
                         cudaFuncAttributeMaxDynamicSharedMemorySize, SM_TOT);

    transpose_kernel<<<512, 256>>>(x);
    wsplit_kernel<<<198, 256>>>(wd, wo);
    fused_deform_kernel<<<512, 256, SM_TOT>>>(bo, bd, out);
}